// round 3
// baseline (speedup 1.0000x reference)
#include <cuda_runtime.h>
#include <math.h>

// ---------------- problem constants ----------------
#define NT 20000
#define NC 200000
#define NF 40000
#define E_HC 200000
#define E_BT 200000
#define E_IS 80000
#define E_PT 80000
#define FH 256   // H*D

// ---------------- scratch (single __device__ array, offsets in floats) ----
// feat_t NT*256 | feat_c NC*256 | feat_f NF*256 | xl NC*256 | xr NC*256 |
// oc1 NC*256 | oc2 NC*256 | ot NT*256 | of NF*256 | logit E*4 | segm NC*4 | segd NC*4
#define OFF_FEAT_T 0ull
#define OFF_FEAT_C (OFF_FEAT_T + (size_t)NT*FH)
#define OFF_FEAT_F (OFF_FEAT_C + (size_t)NC*FH)
#define OFF_XL     (OFF_FEAT_F + (size_t)NF*FH)
#define OFF_XR     (OFF_XL     + (size_t)NC*FH)
#define OFF_OC1    (OFF_XR     + (size_t)NC*FH)
#define OFF_OC2    (OFF_OC1    + (size_t)NC*FH)
#define OFF_OT     (OFF_OC2    + (size_t)NC*FH)
#define OFF_OF     (OFF_OT     + (size_t)NT*FH)
#define OFF_LOGIT  (OFF_OF     + (size_t)NF*FH)
#define OFF_SEGM   (OFF_LOGIT  + (size_t)E_HC*4)
#define OFF_SEGD   (OFF_SEGM   + (size_t)NC*4)
#define SCRATCH_TOTAL (OFF_SEGD + (size_t)NC*4)

__device__ float g_scratch[SCRATCH_TOTAL];

// ---------------- GEMM: C = act(A[M,K] @ B[K,N] + bias) ----------------
// BM=128, BK=16, TM=8; BN/TN templated (64/4 for input proj, 128/8 otherwise).
template<int ACT, int BN>
__global__ __launch_bounds__(256)
void gemm_kernel(const float* __restrict__ A, const float* __restrict__ B,
                 const float* __restrict__ bias, float* __restrict__ C,
                 int M, int K, int N)
{
    constexpr int BM = 128, BK = 16;
    constexpr int TM = 8, TN = BN / 16;
    __shared__ float As[BK][BM];
    __shared__ float Bs[BK][BN];

    const int tid = threadIdx.x;
    const int tn = tid & 15;
    const int tm = tid >> 4;
    const int rowBase = blockIdx.y * BM;
    const int colBase = blockIdx.x * BN;

    float acc[TM][TN];
#pragma unroll
    for (int i = 0; i < TM; i++)
#pragma unroll
        for (int j = 0; j < TN; j++) acc[i][j] = 0.f;

    const int nTiles = K / BK;
    for (int t = 0; t < nTiles; t++) {
        // A tile: 128x16, vectorized along K; 2 float4 per thread
#pragma unroll
        for (int i = 0; i < 2; i++) {
            int li = tid + i * 256;          // 0..511
            int m  = li >> 2;                // 0..127
            int k4 = (li & 3) << 2;          // 0,4,8,12
            float4 v = make_float4(0.f, 0.f, 0.f, 0.f);
            int gm = rowBase + m;
            if (gm < M)
                v = *(const float4*)(A + (size_t)gm * K + t * BK + k4);
            As[k4 + 0][m] = v.x; As[k4 + 1][m] = v.y;
            As[k4 + 2][m] = v.z; As[k4 + 3][m] = v.w;
        }
        // B tile: 16 x BN; BN/64 float4 per thread
#pragma unroll
        for (int i = 0; i < BN / 64; i++) {
            int li = tid + i * 256;          // 0 .. BK*BN/4-1
            int k  = li / (BN / 4);
            int n4 = (li % (BN / 4)) << 2;
            *(float4*)&Bs[k][n4] =
                *(const float4*)(B + (size_t)(t * BK + k) * N + colBase + n4);
        }
        __syncthreads();
#pragma unroll
        for (int k = 0; k < BK; k++) {
            float a[TM], b[TN];
#pragma unroll
            for (int i = 0; i < TM; i += 4) {
                float4 v = *(float4*)&As[k][tm * TM + i];
                a[i] = v.x; a[i + 1] = v.y; a[i + 2] = v.z; a[i + 3] = v.w;
            }
#pragma unroll
            for (int j = 0; j < TN; j += 4) {
                float4 v = *(float4*)&Bs[k][tn * TN + j];
                b[j] = v.x; b[j + 1] = v.y; b[j + 2] = v.z; b[j + 3] = v.w;
            }
#pragma unroll
            for (int i = 0; i < TM; i++)
#pragma unroll
                for (int j = 0; j < TN; j++)
                    acc[i][j] = fmaf(a[i], b[j], acc[i][j]);
        }
        __syncthreads();
    }
    // epilogue
#pragma unroll
    for (int i = 0; i < TM; i++) {
        int row = rowBase + tm * TM + i;
        if (row >= M) continue;
#pragma unroll
        for (int j = 0; j < TN; j += 4) {
            int col = colBase + tn * TN + j;
            float4 v = make_float4(acc[i][j], acc[i][j + 1], acc[i][j + 2], acc[i][j + 3]);
            if (bias) {
                v.x += bias[col]; v.y += bias[col + 1];
                v.z += bias[col + 2]; v.w += bias[col + 3];
            }
            if (ACT == 1) {   // leaky_relu 0.01
                v.x = v.x > 0.f ? v.x : 0.01f * v.x;
                v.y = v.y > 0.f ? v.y : 0.01f * v.y;
                v.z = v.z > 0.f ? v.z : 0.01f * v.z;
                v.w = v.w > 0.f ? v.w : 0.01f * v.w;
            }
            *(float4*)(C + (size_t)row * N + col) = v;
        }
    }
}

// ---------------- edge kernels ----------------
__device__ __forceinline__ void atomicMaxF(float* addr, float val)
{
    int old = __float_as_int(*addr);
    while (__int_as_float(old) < val) {
        int assumed = old;
        old = atomicCAS((int*)addr, assumed, __float_as_int(val));
        if (old == assumed) break;
    }
}

// Pass 1: logits + segment max. One warp per edge; lane owns 8 contiguous
// channels (all in head lane>>3); 3-step shuffle reduce within 8-lane groups.
__global__ void edge_logits_kernel(const float* __restrict__ xl, const float* __restrict__ xr,
                                   const int* __restrict__ src, const int* __restrict__ dst,
                                   const float* __restrict__ att,
                                   float* __restrict__ logit, float* __restrict__ segm, int E)
{
    int e = blockIdx.x * 8 + (threadIdx.x >> 5);
    if (e >= E) return;
    int lane = threadIdx.x & 31;
    int s = src[e], d = dst[e];
    const float4* pl = (const float4*)(xl + (size_t)s * FH) + lane * 2;
    const float4* pr = (const float4*)(xr + (size_t)d * FH) + lane * 2;
    const float4* pa = (const float4*)att + lane * 2;
    float sum = 0.f;
#pragma unroll
    for (int i = 0; i < 2; i++) {
        float4 l4 = pl[i], r4 = pr[i], a4 = pa[i];
        float v;
        v = l4.x + r4.x; v = v > 0.f ? v : 0.2f * v; sum += v * a4.x;
        v = l4.y + r4.y; v = v > 0.f ? v : 0.2f * v; sum += v * a4.y;
        v = l4.z + r4.z; v = v > 0.f ? v : 0.2f * v; sum += v * a4.z;
        v = l4.w + r4.w; v = v > 0.f ? v : 0.2f * v; sum += v * a4.w;
    }
    sum += __shfl_xor_sync(0xffffffffu, sum, 1);
    sum += __shfl_xor_sync(0xffffffffu, sum, 2);
    sum += __shfl_xor_sync(0xffffffffu, sum, 4);
    if ((lane & 7) == 0) {
        int h = lane >> 3;
        logit[(size_t)e * 4 + h] = sum;
        atomicMaxF(&segm[(size_t)d * 4 + h], sum);
    }
}

// Pass 2: z = exp(logit - m[dst]); den += z. One thread per (edge, head).
__global__ void edge_exp_kernel(const int* __restrict__ dst, const float* __restrict__ segm,
                                float* __restrict__ logit, float* __restrict__ segd, int E)
{
    int i = blockIdx.x * blockDim.x + threadIdx.x;
    if (i >= E * 4) return;
    int e = i >> 2, h = i & 3;
    int d = dst[e];
    float z = expf(logit[i] - segm[(size_t)d * 4 + h]);
    logit[i] = z;
    atomicAdd(&segd[(size_t)d * 4 + h], z);
}

// Pass 3: out[dst] += xl[src] * alpha. Warp per edge, 4-wide RED atomics.
__global__ void edge_scatter_kernel(const float* __restrict__ xl,
                                    const int* __restrict__ src, const int* __restrict__ dst,
                                    const float* __restrict__ logit, const float* __restrict__ segd,
                                    float* __restrict__ out, int E)
{
    int e = blockIdx.x * 8 + (threadIdx.x >> 5);
    if (e >= E) return;
    int lane = threadIdx.x & 31;
    int s = src[e], d = dst[e];
    int h = lane >> 3;
    float alpha = logit[(size_t)e * 4 + h] / segd[(size_t)d * 4 + h];
    const float4* pl = (const float4*)(xl + (size_t)s * FH) + lane * 2;
    float* po = out + (size_t)d * FH + lane * 8;
#pragma unroll
    for (int i = 0; i < 2; i++) {
        float4 v = pl[i];
        v.x *= alpha; v.y *= alpha; v.z *= alpha; v.w *= alpha;
        asm volatile("red.global.add.v4.f32 [%0], {%1,%2,%3,%4};"
                     :: "l"(po + i * 4), "f"(v.x), "f"(v.y), "f"(v.z), "f"(v.w)
                     : "memory");
    }
}

// ---------------- elementwise helpers ----------------
__global__ void fill_val_kernel(float* __restrict__ p, int n, float v)
{
    int i = blockIdx.x * blockDim.x + threadIdx.x;
    if (i < n) p[i] = v;
}

// out[n, 0:256] = bias[0:256] broadcast (n4 = rows*64 float4s)
__global__ void fill_bias_kernel(float* __restrict__ out, const float* __restrict__ bias, int n4)
{
    int i = blockIdx.x * blockDim.x + threadIdx.x;
    if (i < n4) ((float4*)out)[i] = ((const float4*)bias)[i & 63];
}

__device__ __forceinline__ float eluf(float x) { return x > 0.f ? x : expm1f(x); }

__global__ void elu_kernel(const float* __restrict__ a, float* __restrict__ o, int n4)
{
    int i = blockIdx.x * blockDim.x + threadIdx.x;
    if (i >= n4) return;
    float4 v = ((const float4*)a)[i];
    v.x = eluf(v.x); v.y = eluf(v.y); v.z = eluf(v.z); v.w = eluf(v.w);
    ((float4*)o)[i] = v;
}

__global__ void elu_mean_kernel(const float* __restrict__ a, const float* __restrict__ b,
                                float* __restrict__ o, int n4)
{
    int i = blockIdx.x * blockDim.x + threadIdx.x;
    if (i >= n4) return;
    float4 x = ((const float4*)a)[i];
    float4 y = ((const float4*)b)[i];
    float4 v;
    v.x = eluf(0.5f * (x.x + y.x));
    v.y = eluf(0.5f * (x.y + y.y));
    v.z = eluf(0.5f * (x.z + y.z));
    v.w = eluf(0.5f * (x.w + y.w));
    ((float4*)o)[i] = v;
}

// ---------------- host orchestration ----------------
static void run_conv(const float* fs, int nS, const float* fd, int nD, int Kin,
                     const float* Wl, const float* Wr, const float* att, const float* bias,
                     const int* src, const int* dst, int E,
                     float* xl, float* xr, float* logit, float* segm, float* segd,
                     float* out)
{
    gemm_kernel<0, 128><<<dim3(2, (nS + 127) / 128), 256>>>(fs, Wl, nullptr, xl, nS, Kin, FH);
    gemm_kernel<0, 128><<<dim3(2, (nD + 127) / 128), 256>>>(fd, Wr, nullptr, xr, nD, Kin, FH);
    fill_val_kernel<<<(nD * 4 + 255) / 256, 256>>>(segm, nD * 4, -1e30f);
    fill_val_kernel<<<(nD * 4 + 255) / 256, 256>>>(segd, nD * 4, 0.f);
    fill_bias_kernel<<<(nD * 64 + 255) / 256, 256>>>(out, bias, nD * 64);
    edge_logits_kernel<<<(E + 7) / 8, 256>>>(xl, xr, src, dst, att, logit, segm, E);
    edge_exp_kernel<<<(E * 4 + 255) / 256, 256>>>(dst, segm, logit, segd, E);
    edge_scatter_kernel<<<(E + 7) / 8, 256>>>(xl, src, dst, logit, segd, out, E);
}

extern "C" void kernel_launch(void* const* d_in, const int* in_sizes, int n_in,
                              void* d_out, int out_size)
{
    (void)in_sizes; (void)n_in; (void)out_size;
    const float* x_table  = (const float*)d_in[0];
    const float* x_column = (const float*)d_in[1];
    const float* x_fk     = (const float*)d_in[2];
    const float* lin_w    = (const float*)d_in[3];   // (3,256,64)
    const float* lin_b    = (const float*)d_in[4];   // (3,64)
    const float* out_w    = (const float*)d_in[5];   // (3,256,256)
    const float* out_b    = (const float*)d_in[6];   // (3,256)
    const float* Wl0      = (const float*)d_in[7];   // (4,64,256)
    const float* Wr0      = (const float*)d_in[8];
    const float* att0     = (const float*)d_in[9];   // (4,4,64)
    const float* b0       = (const float*)d_in[10];  // (4,256)
    const float* Wl1      = (const float*)d_in[11];  // (4,256,256)
    const float* Wr1      = (const float*)d_in[12];
    const float* att1     = (const float*)d_in[13];
    const float* b1       = (const float*)d_in[14];
    const int* src_hc = (const int*)d_in[15];
    const int* dst_hc = (const int*)d_in[16];
    const int* src_bt = (const int*)d_in[17];
    const int* dst_bt = (const int*)d_in[18];
    const int* src_is = (const int*)d_in[19];
    const int* dst_is = (const int*)d_in[20];
    const int* src_pt = (const int*)d_in[21];
    const int* dst_pt = (const int*)d_in[22];

    float* base = nullptr;
    cudaGetSymbolAddress((void**)&base, g_scratch);
    float* feat_t = base + OFF_FEAT_T;
    float* feat_c = base + OFF_FEAT_C;
    float* feat_f = base + OFF_FEAT_F;
    float* xl     = base + OFF_XL;
    float* xr     = base + OFF_XR;
    float* oc1    = base + OFF_OC1;
    float* oc2    = base + OFF_OC2;
    float* ot     = base + OFF_OT;
    float* of     = base + OFF_OF;
    float* logit  = base + OFF_LOGIT;
    float* segm   = base + OFF_SEGM;
    float* segd   = base + OFF_SEGD;

    // input projections (K=256 -> N=64, leaky_relu 0.01)
    gemm_kernel<1, 64><<<dim3(1, (NT + 127) / 128), 256>>>(x_table,  lin_w,             lin_b,       feat_t, NT, 256, 64);
    gemm_kernel<1, 64><<<dim3(1, (NC + 127) / 128), 256>>>(x_column, lin_w + 256 * 64,  lin_b + 64,  feat_c, NC, 256, 64);
    gemm_kernel<1, 64><<<dim3(1, (NF + 127) / 128), 256>>>(x_fk,     lin_w + 2*256*64,  lin_b + 128, feat_f, NF, 256, 64);

    for (int l = 0; l < 2; l++) {
        int Kin = (l == 0) ? 64 : 256;
        const float* Wl  = l ? Wl1  : Wl0;
        const float* Wr  = l ? Wr1  : Wr0;
        const float* att = l ? att1 : att0;
        const float* bb  = l ? b1   : b0;
        size_t ws = (size_t)Kin * FH;

        // hc: table -> column (dst NC)
        run_conv(feat_t, NT, feat_c, NC, Kin, Wl + 0 * ws, Wr + 0 * ws, att + 0,   bb + 0,
                 src_hc, dst_hc, E_HC, xl, xr, logit, segm, segd, oc1);
        // bt: column -> table (dst NT)
        run_conv(feat_c, NC, feat_t, NT, Kin, Wl + 1 * ws, Wr + 1 * ws, att + 256, bb + 256,
                 src_bt, dst_bt, E_BT, xl, xr, logit, segm, segd, ot);
        // is: column -> fk (dst NF)
        run_conv(feat_c, NC, feat_f, NF, Kin, Wl + 2 * ws, Wr + 2 * ws, att + 512, bb + 512,
                 src_is, dst_is, E_IS, xl, xr, logit, segm, segd, of);
        // pt: fk -> column (dst NC)
        run_conv(feat_f, NF, feat_c, NC, Kin, Wl + 3 * ws, Wr + 3 * ws, att + 768, bb + 768,
                 src_pt, dst_pt, E_PT, xl, xr, logit, segm, segd, oc2);

        // combine + elu -> next-layer features (widths all 256 now)
        elu_kernel<<<(NT * 64 + 255) / 256, 256>>>(ot, feat_t, NT * 64);
        elu_mean_kernel<<<(NC * 64 + 255) / 256, 256>>>(oc1, oc2, feat_c, NC * 64);
        elu_kernel<<<(NF * 64 + 255) / 256, 256>>>(of, feat_f, NF * 64);
    }

    // output heads -> d_out (xt | xc | xf), fp32
    float* out = (float*)d_out;
    gemm_kernel<0, 128><<<dim3(2, (NT + 127) / 128), 256>>>(feat_t, out_w,              out_b,       out,                        NT, 256, 256);
    gemm_kernel<0, 128><<<dim3(2, (NC + 127) / 128), 256>>>(feat_c, out_w + 256 * 256,  out_b + 256, out + (size_t)NT * 256,     NC, 256, 256);
    gemm_kernel<0, 128><<<dim3(2, (NF + 127) / 128), 256>>>(feat_f, out_w + 2*256*256,  out_b + 512, out + (size_t)(NT+NC)*256,  NF, 256, 256);
}

// round 4
// speedup vs baseline: 2.1497x; 2.1497x over previous
#include <cuda_runtime.h>
#include <math.h>
#include <stdint.h>

// ---------------- problem constants ----------------
#define NT 20000
#define NC 200000
#define NF 40000
#define E_HC 200000
#define E_BT 200000
#define E_IS 80000
#define E_PT 80000
#define FH 256   // H*D

// ---------------- scratch (single __device__ array, offsets in floats) ----
#define OFF_FEAT_T 0ull
#define OFF_FEAT_C (OFF_FEAT_T + (size_t)NT*FH)
#define OFF_FEAT_F (OFF_FEAT_C + (size_t)NC*FH)
#define OFF_XL     (OFF_FEAT_F + (size_t)NF*FH)
#define OFF_XR     (OFF_XL     + (size_t)NC*FH)
#define OFF_OC1    (OFF_XR     + (size_t)NC*FH)
#define OFF_OC2    (OFF_OC1    + (size_t)NC*FH)
#define OFF_OT     (OFF_OC2    + (size_t)NC*FH)
#define OFF_OF     (OFF_OT     + (size_t)NT*FH)
#define OFF_LOGIT  (OFF_OF     + (size_t)NF*FH)
#define OFF_SEGM   (OFF_LOGIT  + (size_t)E_HC*4)
#define OFF_SEGD   (OFF_SEGM   + (size_t)NC*4)
#define SCRATCH_TOTAL (OFF_SEGD + (size_t)NC*4)

__device__ float g_scratch[SCRATCH_TOTAL];

// ---------------- tf32 tensor-core GEMM ----------------
// C[M,N] = act(A[M,K] @ B[K,N] + bias), all row-major fp32, tf32 multiplicands.
// BM=128, BK=32, 256 threads (8 warps). Double-buffered cp.async smem pipeline.
// A smem padded to BKP=36 (≡4 mod 32) -> conflict-free A fragment LDS.
// B smem padded to BNP=BN+8 (≡8 mod 32) -> conflict-free B fragment LDS.

__device__ __forceinline__ void cp_async16(void* dst, const void* src)
{
    uint32_t d = (uint32_t)__cvta_generic_to_shared(dst);
    asm volatile("cp.async.cg.shared.global [%0], [%1], 16;\n" :: "r"(d), "l"(src));
}
__device__ __forceinline__ void cp_commit() { asm volatile("cp.async.commit_group;\n" ::: "memory"); }
__device__ __forceinline__ void cp_wait0()  { asm volatile("cp.async.wait_group 0;\n" ::: "memory"); }

__device__ __forceinline__ uint32_t cvt_tf32(float x)
{
    uint32_t r; asm("cvt.rna.tf32.f32 %0, %1;" : "=r"(r) : "f"(x)); return r;
}

__device__ __forceinline__ void mma_tf32(float* c, const uint32_t* a, const uint32_t* b)
{
    asm volatile("mma.sync.aligned.m16n8k8.row.col.f32.tf32.tf32.f32 "
                 "{%0,%1,%2,%3}, {%4,%5,%6,%7}, {%8,%9}, {%0,%1,%2,%3};"
                 : "+f"(c[0]), "+f"(c[1]), "+f"(c[2]), "+f"(c[3])
                 : "r"(a[0]), "r"(a[1]), "r"(a[2]), "r"(a[3]), "r"(b[0]), "r"(b[1]));
}

template<int ACT, int BN, int WARPS_M, int WARPS_N>
__global__ void __launch_bounds__(256, 2)
gemm_tf32(const float* __restrict__ A, const float* __restrict__ B,
          const float* __restrict__ bias, float* __restrict__ C,
          int M, int K, int N)
{
    constexpr int BM = 128, BK = 32;
    constexpr int BKP = 36;           // BK+4, ≡4 mod 32
    constexpr int BNP = BN + 8;       // ≡8 mod 32
    constexpr int WM = BM / WARPS_M, WN = BN / WARPS_N;
    constexpr int MI = WM / 16, NI = WN / 8;
    constexpr int A_STAGE = BM * BKP;
    constexpr int B_STAGE = BK * BNP;

    extern __shared__ float sm[];
    float* Asm = sm;                   // 2 stages
    float* Bsm = sm + 2 * A_STAGE;     // 2 stages

    const int tid  = threadIdx.x;
    const int lane = tid & 31;
    const int warp = tid >> 5;
    const int g    = lane >> 2;        // 0..7
    const int tig  = lane & 3;         // 0..3
    const int warpM = warp % WARPS_M;
    const int warpN = warp / WARPS_M;
    const int rowBase = blockIdx.y * BM;
    const int colBase = blockIdx.x * BN;

    float acc[MI][NI][4];
#pragma unroll
    for (int mi = 0; mi < MI; mi++)
#pragma unroll
        for (int ni = 0; ni < NI; ni++)
#pragma unroll
            for (int q = 0; q < 4; q++) acc[mi][ni][q] = 0.f;

    auto load_tile = [&](int t, int s) {
        // A tile: BM x BK = 1024 float4, 4 per thread
#pragma unroll
        for (int i = 0; i < 4; i++) {
            int li = tid + i * 256;
            int m = li >> 3;
            int k4 = (li & 7) << 2;
            int gm = rowBase + m;
            if (gm >= M) gm = M - 1;            // clamp: row m only feeds C row m (masked)
            cp_async16(Asm + s * A_STAGE + m * BKP + k4,
                       A + (size_t)gm * K + t * BK + k4);
        }
        // B tile: BK x BN -> BK*BN/1024 float4 per thread (4 for BN=128, 2 for BN=64)
#pragma unroll
        for (int i = 0; i < (BK * BN) / 1024; i++) {
            int li = tid + i * 256;
            int k = li / (BN / 4);
            int n4 = (li % (BN / 4)) << 2;
            cp_async16(Bsm + s * B_STAGE + k * BNP + n4,
                       B + (size_t)(t * BK + k) * N + colBase + n4);
        }
        cp_commit();
    };

    load_tile(0, 0);
    cp_wait0();
    __syncthreads();

    const int nT = K / BK;
    int buf = 0;
    for (int t = 0; t < nT; t++) {
        if (t + 1 < nT) load_tile(t + 1, buf ^ 1);

        const float* Asb = Asm + buf * A_STAGE;
        const float* Bsb = Bsm + buf * B_STAGE;
#pragma unroll
        for (int k8 = 0; k8 < BK / 8; k8++) {
            const int kk = k8 * 8;
            uint32_t a[MI][4], b[NI][2];
#pragma unroll
            for (int mi = 0; mi < MI; mi++) {
                const float* ap = Asb + (warpM * WM + mi * 16 + g) * BKP + kk + tig;
                a[mi][0] = cvt_tf32(ap[0]);
                a[mi][1] = cvt_tf32(ap[8 * BKP]);
                a[mi][2] = cvt_tf32(ap[4]);
                a[mi][3] = cvt_tf32(ap[8 * BKP + 4]);
            }
#pragma unroll
            for (int ni = 0; ni < NI; ni++) {
                const float* bp = Bsb + (kk + tig) * BNP + warpN * WN + ni * 8 + g;
                b[ni][0] = cvt_tf32(bp[0]);
                b[ni][1] = cvt_tf32(bp[4 * BNP]);
            }
#pragma unroll
            for (int mi = 0; mi < MI; mi++)
#pragma unroll
                for (int ni = 0; ni < NI; ni++)
                    mma_tf32(acc[mi][ni], a[mi], b[ni]);
        }

        if (t + 1 < nT) cp_wait0();
        __syncthreads();
        buf ^= 1;
    }

    // epilogue
#pragma unroll
    for (int mi = 0; mi < MI; mi++) {
        int row0 = rowBase + warpM * WM + mi * 16 + g;
#pragma unroll
        for (int ni = 0; ni < NI; ni++) {
            int col = colBase + warpN * WN + ni * 8 + tig * 2;
            float bx = 0.f, by = 0.f;
            if (bias) { bx = bias[col]; by = bias[col + 1]; }
            float2 v;
            v.x = acc[mi][ni][0] + bx;
            v.y = acc[mi][ni][1] + by;
            if (ACT == 1) {
                v.x = v.x > 0.f ? v.x : 0.01f * v.x;
                v.y = v.y > 0.f ? v.y : 0.01f * v.y;
            }
            if (row0 < M) *(float2*)(C + (size_t)row0 * N + col) = v;
            v.x = acc[mi][ni][2] + bx;
            v.y = acc[mi][ni][3] + by;
            if (ACT == 1) {
                v.x = v.x > 0.f ? v.x : 0.01f * v.x;
                v.y = v.y > 0.f ? v.y : 0.01f * v.y;
            }
            if (row0 + 8 < M) *(float2*)(C + (size_t)(row0 + 8) * N + col) = v;
        }
    }
}

// smem byte sizes per instantiation
#define SMEM_BN128 ((2*128*36 + 2*32*136) * 4)   // 71680
#define SMEM_BN64  ((2*128*36 + 2*32*72)  * 4)   // 55296

// ---------------- edge kernels (unchanged, proven correct) ----------------
__device__ __forceinline__ void atomicMaxF(float* addr, float val)
{
    int old = __float_as_int(*addr);
    while (__int_as_float(old) < val) {
        int assumed = old;
        old = atomicCAS((int*)addr, assumed, __float_as_int(val));
        if (old == assumed) break;
    }
}

__global__ void edge_logits_kernel(const float* __restrict__ xl, const float* __restrict__ xr,
                                   const int* __restrict__ src, const int* __restrict__ dst,
                                   const float* __restrict__ att,
                                   float* __restrict__ logit, float* __restrict__ segm, int E)
{
    int e = blockIdx.x * 8 + (threadIdx.x >> 5);
    if (e >= E) return;
    int lane = threadIdx.x & 31;
    int s = src[e], d = dst[e];
    const float4* pl = (const float4*)(xl + (size_t)s * FH) + lane * 2;
    const float4* pr = (const float4*)(xr + (size_t)d * FH) + lane * 2;
    const float4* pa = (const float4*)att + lane * 2;
    float sum = 0.f;
#pragma unroll
    for (int i = 0; i < 2; i++) {
        float4 l4 = pl[i], r4 = pr[i], a4 = pa[i];
        float v;
        v = l4.x + r4.x; v = v > 0.f ? v : 0.2f * v; sum += v * a4.x;
        v = l4.y + r4.y; v = v > 0.f ? v : 0.2f * v; sum += v * a4.y;
        v = l4.z + r4.z; v = v > 0.f ? v : 0.2f * v; sum += v * a4.z;
        v = l4.w + r4.w; v = v > 0.f ? v : 0.2f * v; sum += v * a4.w;
    }
    sum += __shfl_xor_sync(0xffffffffu, sum, 1);
    sum += __shfl_xor_sync(0xffffffffu, sum, 2);
    sum += __shfl_xor_sync(0xffffffffu, sum, 4);
    if ((lane & 7) == 0) {
        int h = lane >> 3;
        logit[(size_t)e * 4 + h] = sum;
        atomicMaxF(&segm[(size_t)d * 4 + h], sum);
    }
}

__global__ void edge_exp_kernel(const int* __restrict__ dst, const float* __restrict__ segm,
                                float* __restrict__ logit, float* __restrict__ segd, int E)
{
    int i = blockIdx.x * blockDim.x + threadIdx.x;
    if (i >= E * 4) return;
    int e = i >> 2, h = i & 3;
    int d = dst[e];
    float z = expf(logit[i] - segm[(size_t)d * 4 + h]);
    logit[i] = z;
    atomicAdd(&segd[(size_t)d * 4 + h], z);
}

__global__ void edge_scatter_kernel(const float* __restrict__ xl,
                                    const int* __restrict__ src, const int* __restrict__ dst,
                                    const float* __restrict__ logit, const float* __restrict__ segd,
                                    float* __restrict__ out, int E)
{
    int e = blockIdx.x * 8 + (threadIdx.x >> 5);
    if (e >= E) return;
    int lane = threadIdx.x & 31;
    int s = src[e], d = dst[e];
    int h = lane >> 3;
    float alpha = logit[(size_t)e * 4 + h] / segd[(size_t)d * 4 + h];
    const float4* pl = (const float4*)(xl + (size_t)s * FH) + lane * 2;
    float* po = out + (size_t)d * FH + lane * 8;
#pragma unroll
    for (int i = 0; i < 2; i++) {
        float4 v = pl[i];
        v.x *= alpha; v.y *= alpha; v.z *= alpha; v.w *= alpha;
        asm volatile("red.global.add.v4.f32 [%0], {%1,%2,%3,%4};"
                     :: "l"(po + i * 4), "f"(v.x), "f"(v.y), "f"(v.z), "f"(v.w)
                     : "memory");
    }
}

// ---------------- elementwise helpers ----------------
__global__ void fill_val_kernel(float* __restrict__ p, int n, float v)
{
    int i = blockIdx.x * blockDim.x + threadIdx.x;
    if (i < n) p[i] = v;
}

__global__ void fill_bias_kernel(float* __restrict__ out, const float* __restrict__ bias, int n4)
{
    int i = blockIdx.x * blockDim.x + threadIdx.x;
    if (i < n4) ((float4*)out)[i] = ((const float4*)bias)[i & 63];
}

__device__ __forceinline__ float eluf(float x) { return x > 0.f ? x : expm1f(x); }

__global__ void elu_kernel(const float* __restrict__ a, float* __restrict__ o, int n4)
{
    int i = blockIdx.x * blockDim.x + threadIdx.x;
    if (i >= n4) return;
    float4 v = ((const float4*)a)[i];
    v.x = eluf(v.x); v.y = eluf(v.y); v.z = eluf(v.z); v.w = eluf(v.w);
    ((float4*)o)[i] = v;
}

__global__ void elu_mean_kernel(const float* __restrict__ a, const float* __restrict__ b,
                                float* __restrict__ o, int n4)
{
    int i = blockIdx.x * blockDim.x + threadIdx.x;
    if (i >= n4) return;
    float4 x = ((const float4*)a)[i];
    float4 y = ((const float4*)b)[i];
    float4 v;
    v.x = eluf(0.5f * (x.x + y.x));
    v.y = eluf(0.5f * (x.y + y.y));
    v.z = eluf(0.5f * (x.z + y.z));
    v.w = eluf(0.5f * (x.w + y.w));
    ((float4*)o)[i] = v;
}

// ---------------- host orchestration ----------------
static void run_conv(const float* fs, int nS, const float* fd, int nD, int Kin,
                     const float* Wl, const float* Wr, const float* att, const float* bias,
                     const int* src, const int* dst, int E,
                     float* xl, float* xr, float* logit, float* segm, float* segd,
                     float* out)
{
    gemm_tf32<0, 128, 2, 4><<<dim3(2, (nS + 127) / 128), 256, SMEM_BN128>>>(fs, Wl, nullptr, xl, nS, Kin, FH);
    gemm_tf32<0, 128, 2, 4><<<dim3(2, (nD + 127) / 128), 256, SMEM_BN128>>>(fd, Wr, nullptr, xr, nD, Kin, FH);
    fill_val_kernel<<<(nD * 4 + 255) / 256, 256>>>(segm, nD * 4, -1e30f);
    fill_val_kernel<<<(nD * 4 + 255) / 256, 256>>>(segd, nD * 4, 0.f);
    fill_bias_kernel<<<(nD * 64 + 255) / 256, 256>>>(out, bias, nD * 64);
    edge_logits_kernel<<<(E + 7) / 8, 256>>>(xl, xr, src, dst, att, logit, segm, E);
    edge_exp_kernel<<<(E * 4 + 255) / 256, 256>>>(dst, segm, logit, segd, E);
    edge_scatter_kernel<<<(E + 7) / 8, 256>>>(xl, src, dst, logit, segd, out, E);
}

extern "C" void kernel_launch(void* const* d_in, const int* in_sizes, int n_in,
                              void* d_out, int out_size)
{
    (void)in_sizes; (void)n_in; (void)out_size;
    const float* x_table  = (const float*)d_in[0];
    const float* x_column = (const float*)d_in[1];
    const float* x_fk     = (const float*)d_in[2];
    const float* lin_w    = (const float*)d_in[3];   // (3,256,64)
    const float* lin_b    = (const float*)d_in[4];   // (3,64)
    const float* out_w    = (const float*)d_in[5];   // (3,256,256)
    const float* out_b    = (const float*)d_in[6];   // (3,256)
    const float* Wl0      = (const float*)d_in[7];   // (4,64,256)
    const float* Wr0      = (const float*)d_in[8];
    const float* att0     = (const float*)d_in[9];   // (4,4,64)
    const float* b0       = (const float*)d_in[10];  // (4,256)
    const float* Wl1      = (const float*)d_in[11];  // (4,256,256)
    const float* Wr1      = (const float*)d_in[12];
    const float* att1     = (const float*)d_in[13];
    const float* b1       = (const float*)d_in[14];
    const int* src_hc = (const int*)d_in[15];
    const int* dst_hc = (const int*)d_in[16];
    const int* src_bt = (const int*)d_in[17];
    const int* dst_bt = (const int*)d_in[18];
    const int* src_is = (const int*)d_in[19];
    const int* dst_is = (const int*)d_in[20];
    const int* src_pt = (const int*)d_in[21];
    const int* dst_pt = (const int*)d_in[22];

    // opt-in to >48KB dynamic smem (idempotent, not an allocation)
    cudaFuncSetAttribute((const void*)gemm_tf32<0, 128, 2, 4>,
                         cudaFuncAttributeMaxDynamicSharedMemorySize, SMEM_BN128);
    cudaFuncSetAttribute((const void*)gemm_tf32<1, 64, 4, 2>,
                         cudaFuncAttributeMaxDynamicSharedMemorySize, SMEM_BN64);

    float* base = nullptr;
    cudaGetSymbolAddress((void**)&base, g_scratch);
    float* feat_t = base + OFF_FEAT_T;
    float* feat_c = base + OFF_FEAT_C;
    float* feat_f = base + OFF_FEAT_F;
    float* xl     = base + OFF_XL;
    float* xr     = base + OFF_XR;
    float* oc1    = base + OFF_OC1;
    float* oc2    = base + OFF_OC2;
    float* ot     = base + OFF_OT;
    float* of     = base + OFF_OF;
    float* logit  = base + OFF_LOGIT;
    float* segm   = base + OFF_SEGM;
    float* segd   = base + OFF_SEGD;

    // input projections (K=256 -> N=64, leaky_relu 0.01)
    gemm_tf32<1, 64, 4, 2><<<dim3(1, (NT + 127) / 128), 256, SMEM_BN64>>>(x_table,  lin_w,            lin_b,       feat_t, NT, 256, 64);
    gemm_tf32<1, 64, 4, 2><<<dim3(1, (NC + 127) / 128), 256, SMEM_BN64>>>(x_column, lin_w + 256*64,   lin_b + 64,  feat_c, NC, 256, 64);
    gemm_tf32<1, 64, 4, 2><<<dim3(1, (NF + 127) / 128), 256, SMEM_BN64>>>(x_fk,     lin_w + 2*256*64, lin_b + 128, feat_f, NF, 256, 64);

    for (int l = 0; l < 2; l++) {
        int Kin = (l == 0) ? 64 : 256;
        const float* Wl  = l ? Wl1  : Wl0;
        const float* Wr  = l ? Wr1  : Wr0;
        const float* att = l ? att1 : att0;
        const float* bb  = l ? b1   : b0;
        size_t ws = (size_t)Kin * FH;

        run_conv(feat_t, NT, feat_c, NC, Kin, Wl + 0 * ws, Wr + 0 * ws, att + 0,   bb + 0,
                 src_hc, dst_hc, E_HC, xl, xr, logit, segm, segd, oc1);
        run_conv(feat_c, NC, feat_t, NT, Kin, Wl + 1 * ws, Wr + 1 * ws, att + 256, bb + 256,
                 src_bt, dst_bt, E_BT, xl, xr, logit, segm, segd, ot);
        run_conv(feat_c, NC, feat_f, NF, Kin, Wl + 2 * ws, Wr + 2 * ws, att + 512, bb + 512,
                 src_is, dst_is, E_IS, xl, xr, logit, segm, segd, of);
        run_conv(feat_f, NF, feat_c, NC, Kin, Wl + 3 * ws, Wr + 3 * ws, att + 768, bb + 768,
                 src_pt, dst_pt, E_PT, xl, xr, logit, segm, segd, oc2);

        elu_kernel<<<(NT * 64 + 255) / 256, 256>>>(ot, feat_t, NT * 64);
        elu_mean_kernel<<<(NC * 64 + 255) / 256, 256>>>(oc1, oc2, feat_c, NC * 64);
        elu_kernel<<<(NF * 64 + 255) / 256, 256>>>(of, feat_f, NF * 64);
    }

    // output heads -> d_out (xt | xc | xf), fp32
    float* out = (float*)d_out;
    gemm_tf32<0, 128, 2, 4><<<dim3(2, (NT + 127) / 128), 256, SMEM_BN128>>>(feat_t, out_w,             out_b,       out,                       NT, 256, 256);
    gemm_tf32<0, 128, 2, 4><<<dim3(2, (NC + 127) / 128), 256, SMEM_BN128>>>(feat_c, out_w + 256*256,   out_b + 256, out + (size_t)NT * 256,    NC, 256, 256);
    gemm_tf32<0, 128, 2, 4><<<dim3(2, (NF + 127) / 128), 256, SMEM_BN128>>>(feat_f, out_w + 2*256*256, out_b + 512, out + (size_t)(NT+NC)*256, NF, 256, 256);
}

// round 5
// speedup vs baseline: 2.3727x; 1.1038x over previous
#include <cuda_runtime.h>
#include <math.h>
#include <stdint.h>

// ---------------- problem constants ----------------
#define NT 20000
#define NC 200000
#define NF 40000
#define E_HC 200000
#define E_BT 200000
#define E_IS 80000
#define E_PT 80000
#define FH 256   // H*D

// ---------------- scratch (single __device__ array, offsets in floats) ----
#define OFF_FEAT_T 0ull
#define OFF_FEAT_C (OFF_FEAT_T + (size_t)NT*FH)
#define OFF_FEAT_F (OFF_FEAT_C + (size_t)NC*FH)
#define OFF_XL     (OFF_FEAT_F + (size_t)NF*FH)
#define OFF_XR     (OFF_XL     + (size_t)NC*FH)
#define OFF_OC1    (OFF_XR     + (size_t)NC*FH)
#define OFF_OC2    (OFF_OC1    + (size_t)NC*FH)
#define OFF_OT     (OFF_OC2    + (size_t)NC*FH)
#define OFF_OF     (OFF_OT     + (size_t)NT*FH)
#define OFF_LOGIT  (OFF_OF     + (size_t)NF*FH)
#define OFF_SEG    (OFF_LOGIT  + (size_t)E_HC*4)   // segm+segd region, 2*NC*4 floats
// rounded-weight copies
#define RW_LIN  (OFF_SEG + (size_t)NC*8)
#define RW_OUT  (RW_LIN + 49152ull)     // 3*256*64
#define RW_WL0  (RW_OUT + 196608ull)    // 3*256*256
#define RW_WR0  (RW_WL0 + 65536ull)     // 4*64*256
#define RW_WL1  (RW_WR0 + 65536ull)
#define RW_WR1  (RW_WL1 + 262144ull)    // 4*256*256
#define SCRATCH_TOTAL (RW_WR1 + 262144ull)

__device__ float g_scratch[SCRATCH_TOTAL];

// ---------------- small PTX helpers ----------------
__device__ __forceinline__ void cp_async16(void* dst, const void* src)
{
    uint32_t d = (uint32_t)__cvta_generic_to_shared(dst);
    asm volatile("cp.async.cg.shared.global [%0], [%1], 16;\n" :: "r"(d), "l"(src));
}
__device__ __forceinline__ void cp_commit() { asm volatile("cp.async.commit_group;\n" ::: "memory"); }
__device__ __forceinline__ void cp_wait0()  { asm volatile("cp.async.wait_group 0;\n" ::: "memory"); }
__device__ __forceinline__ void cp_wait1()  { asm volatile("cp.async.wait_group 1;\n" ::: "memory"); }

__device__ __forceinline__ uint32_t cvt_tf32(float x)
{
    uint32_t r; asm("cvt.rna.tf32.f32 %0, %1;" : "=r"(r) : "f"(x)); return r;
}
__device__ __forceinline__ float round_tf32(float x) { return __uint_as_float(cvt_tf32(x)); }

__device__ __forceinline__ void mma_tf32(float* c, const uint32_t* a, const uint32_t* b)
{
    asm volatile("mma.sync.aligned.m16n8k8.row.col.f32.tf32.tf32.f32 "
                 "{%0,%1,%2,%3}, {%4,%5,%6,%7}, {%8,%9}, {%0,%1,%2,%3};"
                 : "+f"(c[0]), "+f"(c[1]), "+f"(c[2]), "+f"(c[3])
                 : "r"(a[0]), "r"(a[1]), "r"(a[2]), "r"(a[3]), "r"(b[0]), "r"(b[1]));
}

// monotone float->uint key for atomicMax on signed floats
__device__ __forceinline__ uint32_t fmax_key(float f)
{
    int i = __float_as_int(f);
    return (i >= 0) ? ((uint32_t)i | 0x80000000u) : ~(uint32_t)i;
}
__device__ __forceinline__ float fmax_unkey(uint32_t u)
{
    return (u & 0x80000000u) ? __int_as_float((int)(u & 0x7fffffffu))
                             : __int_as_float((int)~u);
}

// ---------------- tf32 tensor-core GEMM (3-stage cp.async pipeline) --------
// C[M,N] = act(A[M,K] @ B[K,N] + bias). A optionally cvt'd at frag load
// (CVT_A); B must be pre-rounded to tf32. Optional tf32 rounding of output.
template<int CVT_A, int ACT, int ROUND_OUT, int BN, int WARPS_M, int WARPS_N>
__global__ void __launch_bounds__(256, 2)
gemm_tf32(const float* __restrict__ A, const float* __restrict__ B,
          const float* __restrict__ bias, float* __restrict__ C,
          int M, int K, int N)
{
    constexpr int BM = 128, BK = 32;
    constexpr int BKP = 36;           // ≡4 mod 32: conflict-free A frags
    constexpr int BNP = BN + 8;       // ≡8 mod 32: conflict-free B frags
    constexpr int WM = BM / WARPS_M, WN = BN / WARPS_N;
    constexpr int MI = WM / 16, NI = WN / 8;
    constexpr int A_STAGE = BM * BKP;
    constexpr int B_STAGE = BK * BNP;
    constexpr int STAGES = 3;

    extern __shared__ float sm[];
    float* Asm = sm;
    float* Bsm = sm + STAGES * A_STAGE;

    const int tid  = threadIdx.x;
    const int lane = tid & 31;
    const int warp = tid >> 5;
    const int g    = lane >> 2;
    const int tig  = lane & 3;
    const int warpM = warp % WARPS_M;
    const int warpN = warp / WARPS_M;
    const int rowBase = blockIdx.y * BM;
    const int colBase = blockIdx.x * BN;

    float acc[MI][NI][4];
#pragma unroll
    for (int mi = 0; mi < MI; mi++)
#pragma unroll
        for (int ni = 0; ni < NI; ni++)
#pragma unroll
            for (int q = 0; q < 4; q++) acc[mi][ni][q] = 0.f;

    auto load_tile = [&](int t, int s) {
#pragma unroll
        for (int i = 0; i < 4; i++) {
            int li = tid + i * 256;
            int m = li >> 3;
            int k4 = (li & 7) << 2;
            int gm = rowBase + m;
            if (gm >= M) gm = M - 1;
            cp_async16(Asm + s * A_STAGE + m * BKP + k4,
                       A + (size_t)gm * K + t * BK + k4);
        }
#pragma unroll
        for (int i = 0; i < (BK * BN) / 1024; i++) {
            int li = tid + i * 256;
            int k = li / (BN / 4);
            int n4 = (li % (BN / 4)) << 2;
            cp_async16(Bsm + s * B_STAGE + k * BNP + n4,
                       B + (size_t)(t * BK + k) * N + colBase + n4);
        }
        cp_commit();
    };

    const int nT = K / BK;
    load_tile(0, 0);
    if (nT > 1) load_tile(1, 1);

    for (int t = 0; t < nT; t++) {
        if (t + 1 < nT) cp_wait1(); else cp_wait0();
        __syncthreads();
        if (t + 2 < nT) load_tile(t + 2, (t + 2) % STAGES);

        const float* Asb = Asm + (t % STAGES) * A_STAGE;
        const float* Bsb = Bsm + (t % STAGES) * B_STAGE;
#pragma unroll
        for (int k8 = 0; k8 < BK / 8; k8++) {
            const int kk = k8 * 8;
            uint32_t a[MI][4], b[NI][2];
#pragma unroll
            for (int mi = 0; mi < MI; mi++) {
                const float* ap = Asb + (warpM * WM + mi * 16 + g) * BKP + kk + tig;
                if (CVT_A) {
                    a[mi][0] = cvt_tf32(ap[0]);
                    a[mi][1] = cvt_tf32(ap[8 * BKP]);
                    a[mi][2] = cvt_tf32(ap[4]);
                    a[mi][3] = cvt_tf32(ap[8 * BKP + 4]);
                } else {
                    a[mi][0] = __float_as_uint(ap[0]);
                    a[mi][1] = __float_as_uint(ap[8 * BKP]);
                    a[mi][2] = __float_as_uint(ap[4]);
                    a[mi][3] = __float_as_uint(ap[8 * BKP + 4]);
                }
            }
#pragma unroll
            for (int ni = 0; ni < NI; ni++) {
                const float* bp = Bsb + (kk + tig) * BNP + warpN * WN + ni * 8 + g;
                b[ni][0] = __float_as_uint(bp[0]);
                b[ni][1] = __float_as_uint(bp[4 * BNP]);
            }
#pragma unroll
            for (int mi = 0; mi < MI; mi++)
#pragma unroll
                for (int ni = 0; ni < NI; ni++)
                    mma_tf32(acc[mi][ni], a[mi], b[ni]);
        }
    }

    // epilogue
#pragma unroll
    for (int mi = 0; mi < MI; mi++) {
        int row0 = rowBase + warpM * WM + mi * 16 + g;
#pragma unroll
        for (int ni = 0; ni < NI; ni++) {
            int col = colBase + warpN * WN + ni * 8 + tig * 2;
            float bx = 0.f, by = 0.f;
            if (bias) { bx = bias[col]; by = bias[col + 1]; }
            float2 v;
            v.x = acc[mi][ni][0] + bx;
            v.y = acc[mi][ni][1] + by;
            if (ACT == 1) {
                v.x = v.x > 0.f ? v.x : 0.01f * v.x;
                v.y = v.y > 0.f ? v.y : 0.01f * v.y;
            }
            if (ROUND_OUT) { v.x = round_tf32(v.x); v.y = round_tf32(v.y); }
            if (row0 < M) *(float2*)(C + (size_t)row0 * N + col) = v;
            v.x = acc[mi][ni][2] + bx;
            v.y = acc[mi][ni][3] + by;
            if (ACT == 1) {
                v.x = v.x > 0.f ? v.x : 0.01f * v.x;
                v.y = v.y > 0.f ? v.y : 0.01f * v.y;
            }
            if (ROUND_OUT) { v.x = round_tf32(v.x); v.y = round_tf32(v.y); }
            if (row0 + 8 < M) *(float2*)(C + (size_t)(row0 + 8) * N + col) = v;
        }
    }
}

#define SMEM_BN128 (3 * (128*36 + 32*136) * 4)   // 107520
#define SMEM_BN64  (3 * (128*36 + 32*72)  * 4)   // 82944

// ---------------- weight pre-rounding (tf32 RNA) ----------------
__global__ void round_weights_kernel(const float* __restrict__ lw, const float* __restrict__ ow,
                                     const float* __restrict__ wl0, const float* __restrict__ wr0,
                                     const float* __restrict__ wl1, const float* __restrict__ wr1,
                                     float* __restrict__ dst)
{
    int i = blockIdx.x * blockDim.x + threadIdx.x;
    const int s0 = 49152, s1 = 196608, s2 = 65536, s3 = 65536, s4 = 262144, s5 = 262144;
    int j = i;
    float v;
    if (j < s0) v = lw[j];
    else if ((j -= s0) < s1) v = ow[j];
    else if ((j -= s1) < s2) v = wl0[j];
    else if ((j -= s2) < s3) v = wr0[j];
    else if ((j -= s3) < s4) v = wl1[j];
    else if ((j -= s4) < s5) v = wr1[j];
    else return;
    dst[i] = round_tf32(v);
}

// ---------------- edge kernels ----------------
// Pass 1: logits + keyed segment max. One warp per edge.
__global__ void edge_logits_kernel(const float* __restrict__ xl, const float* __restrict__ xr,
                                   const int* __restrict__ src, const int* __restrict__ dst,
                                   const float* __restrict__ att,
                                   float* __restrict__ logit, uint32_t* __restrict__ segm, int E)
{
    int e = blockIdx.x * 8 + (threadIdx.x >> 5);
    if (e >= E) return;
    int lane = threadIdx.x & 31;
    int s = src[e], d = dst[e];
    const float4* pl = (const float4*)(xl + (size_t)s * FH) + lane * 2;
    const float4* pr = (const float4*)(xr + (size_t)d * FH) + lane * 2;
    const float4* pa = (const float4*)att + lane * 2;
    float sum = 0.f;
#pragma unroll
    for (int i = 0; i < 2; i++) {
        float4 l4 = pl[i], r4 = pr[i], a4 = pa[i];
        float v;
        v = l4.x + r4.x; v = v > 0.f ? v : 0.2f * v; sum += v * a4.x;
        v = l4.y + r4.y; v = v > 0.f ? v : 0.2f * v; sum += v * a4.y;
        v = l4.z + r4.z; v = v > 0.f ? v : 0.2f * v; sum += v * a4.z;
        v = l4.w + r4.w; v = v > 0.f ? v : 0.2f * v; sum += v * a4.w;
    }
    sum += __shfl_xor_sync(0xffffffffu, sum, 1);
    sum += __shfl_xor_sync(0xffffffffu, sum, 2);
    sum += __shfl_xor_sync(0xffffffffu, sum, 4);
    if ((lane & 7) == 0) {
        int h = lane >> 3;
        logit[(size_t)e * 4 + h] = sum;
        atomicMax(segm + (size_t)d * 4 + h, fmax_key(sum));
    }
}

// Pass 2: one thread per edge; z = exp(logit - m); den += z (red.v4).
__global__ void edge_exp_kernel(const int* __restrict__ dst, const uint32_t* __restrict__ segm,
                                float* __restrict__ logit, float* __restrict__ segd, int E)
{
    int e = blockIdx.x * blockDim.x + threadIdx.x;
    if (e >= E) return;
    int d = dst[e];
    float4 lg = ((const float4*)logit)[e];
    uint4 mk = ((const uint4*)segm)[d];
    float4 z;
    z.x = expf(lg.x - fmax_unkey(mk.x));
    z.y = expf(lg.y - fmax_unkey(mk.y));
    z.z = expf(lg.z - fmax_unkey(mk.z));
    z.w = expf(lg.w - fmax_unkey(mk.w));
    ((float4*)logit)[e] = z;
    asm volatile("red.global.add.v4.f32 [%0], {%1,%2,%3,%4};"
                 :: "l"(segd + (size_t)d * 4), "f"(z.x), "f"(z.y), "f"(z.z), "f"(z.w)
                 : "memory");
}

// Pass 3: out[dst] += xl[src] * alpha. Warp per edge, 4-wide RED atomics.
__global__ void edge_scatter_kernel(const float* __restrict__ xl,
                                    const int* __restrict__ src, const int* __restrict__ dst,
                                    const float* __restrict__ logit, const float* __restrict__ segd,
                                    float* __restrict__ out, int E)
{
    int e = blockIdx.x * 8 + (threadIdx.x >> 5);
    if (e >= E) return;
    int lane = threadIdx.x & 31;
    int s = src[e], d = dst[e];
    int h = lane >> 3;
    float alpha = logit[(size_t)e * 4 + h] / segd[(size_t)d * 4 + h];
    const float4* pl = (const float4*)(xl + (size_t)s * FH) + lane * 2;
    float* po = out + (size_t)d * FH + lane * 8;
#pragma unroll
    for (int i = 0; i < 2; i++) {
        float4 v = pl[i];
        v.x *= alpha; v.y *= alpha; v.z *= alpha; v.w *= alpha;
        asm volatile("red.global.add.v4.f32 [%0], {%1,%2,%3,%4};"
                     :: "l"(po + i * 4), "f"(v.x), "f"(v.y), "f"(v.z), "f"(v.w)
                     : "memory");
    }
}

// ---------------- fused per-conv init: out=bias bcast, segm/segd=0 --------
__global__ void conv_init_kernel(float* __restrict__ out, const float* __restrict__ bias,
                                 float* __restrict__ segmd, int nD)
{
    int i = blockIdx.x * blockDim.x + threadIdx.x;
    int nb = nD * 64;
    if (i < nb) {
        ((float4*)out)[i] = ((const float4*)bias)[i & 63];
    } else if (i < nb + nD * 2) {
        ((float4*)segmd)[i - nb] = make_float4(0.f, 0.f, 0.f, 0.f);
    }
}

// ---------------- elementwise (outputs tf32-rounded: they feed GEMMs) -----
__device__ __forceinline__ float eluf(float x) { return x > 0.f ? x : expm1f(x); }

__global__ void elu_kernel(const float* __restrict__ a, float* __restrict__ o, int n4)
{
    int i = blockIdx.x * blockDim.x + threadIdx.x;
    if (i >= n4) return;
    float4 v = ((const float4*)a)[i];
    v.x = round_tf32(eluf(v.x)); v.y = round_tf32(eluf(v.y));
    v.z = round_tf32(eluf(v.z)); v.w = round_tf32(eluf(v.w));
    ((float4*)o)[i] = v;
}

__global__ void elu_mean_kernel(const float* __restrict__ a, const float* __restrict__ b,
                                float* __restrict__ o, int n4)
{
    int i = blockIdx.x * blockDim.x + threadIdx.x;
    if (i >= n4) return;
    float4 x = ((const float4*)a)[i];
    float4 y = ((const float4*)b)[i];
    float4 v;
    v.x = round_tf32(eluf(0.5f * (x.x + y.x)));
    v.y = round_tf32(eluf(0.5f * (x.y + y.y)));
    v.z = round_tf32(eluf(0.5f * (x.z + y.z)));
    v.w = round_tf32(eluf(0.5f * (x.w + y.w)));
    ((float4*)o)[i] = v;
}

// ---------------- host orchestration ----------------
static void run_conv(const float* fs, int nS, const float* fd, int nD, int Kin,
                     const float* Wl, const float* Wr, const float* att, const float* bias,
                     const int* src, const int* dst, int E,
                     float* xl, float* xr, float* logit, float* segbase,
                     float* out)
{
    float* segm = segbase;                 // nD*4 uint keys
    float* segd = segbase + (size_t)nD * 4;
    gemm_tf32<0, 0, 0, 128, 2, 4><<<dim3(2, (nS + 127) / 128), 256, SMEM_BN128>>>(fs, Wl, nullptr, xl, nS, Kin, FH);
    gemm_tf32<0, 0, 0, 128, 2, 4><<<dim3(2, (nD + 127) / 128), 256, SMEM_BN128>>>(fd, Wr, nullptr, xr, nD, Kin, FH);
    conv_init_kernel<<<(nD * 66 + 255) / 256, 256>>>(out, bias, segm, nD);
    edge_logits_kernel<<<(E + 7) / 8, 256>>>(xl, xr, src, dst, att, logit, (uint32_t*)segm, E);
    edge_exp_kernel<<<(E + 255) / 256, 256>>>(dst, (const uint32_t*)segm, logit, segd, E);
    edge_scatter_kernel<<<(E + 7) / 8, 256>>>(xl, src, dst, logit, segd, out, E);
}

extern "C" void kernel_launch(void* const* d_in, const int* in_sizes, int n_in,
                              void* d_out, int out_size)
{
    (void)in_sizes; (void)n_in; (void)out_size;
    const float* x_table  = (const float*)d_in[0];
    const float* x_column = (const float*)d_in[1];
    const float* x_fk     = (const float*)d_in[2];
    const float* lin_w    = (const float*)d_in[3];   // (3,256,64)
    const float* lin_b    = (const float*)d_in[4];   // (3,64)
    const float* out_w    = (const float*)d_in[5];   // (3,256,256)
    const float* out_b    = (const float*)d_in[6];   // (3,256)
    const float* Wl0      = (const float*)d_in[7];   // (4,64,256)
    const float* Wr0      = (const float*)d_in[8];
    const float* att0     = (const float*)d_in[9];   // (4,4,64)
    const float* b0       = (const float*)d_in[10];  // (4,256)
    const float* Wl1      = (const float*)d_in[11];  // (4,256,256)
    const float* Wr1      = (const float*)d_in[12];
    const float* att1     = (const float*)d_in[13];
    const float* b1       = (const float*)d_in[14];
    const int* src_hc = (const int*)d_in[15];
    const int* dst_hc = (const int*)d_in[16];
    const int* src_bt = (const int*)d_in[17];
    const int* dst_bt = (const int*)d_in[18];
    const int* src_is = (const int*)d_in[19];
    const int* dst_is = (const int*)d_in[20];
    const int* src_pt = (const int*)d_in[21];
    const int* dst_pt = (const int*)d_in[22];

    cudaFuncSetAttribute((const void*)gemm_tf32<0, 0, 0, 128, 2, 4>,
                         cudaFuncAttributeMaxDynamicSharedMemorySize, SMEM_BN128);
    cudaFuncSetAttribute((const void*)gemm_tf32<1, 1, 1, 64, 4, 2>,
                         cudaFuncAttributeMaxDynamicSharedMemorySize, SMEM_BN64);

    float* base = nullptr;
    cudaGetSymbolAddress((void**)&base, g_scratch);
    float* feat_t = base + OFF_FEAT_T;
    float* feat_c = base + OFF_FEAT_C;
    float* feat_f = base + OFF_FEAT_F;
    float* xl     = base + OFF_XL;
    float* xr     = base + OFF_XR;
    float* oc1    = base + OFF_OC1;
    float* oc2    = base + OFF_OC2;
    float* ot     = base + OFF_OT;
    float* of     = base + OFF_OF;
    float* logit  = base + OFF_LOGIT;
    float* seg    = base + OFF_SEG;
    float* rlin   = base + RW_LIN;
    float* rout   = base + RW_OUT;
    float* rwl0   = base + RW_WL0;
    float* rwr0   = base + RW_WR0;
    float* rwl1   = base + RW_WL1;
    float* rwr1   = base + RW_WR1;

    // pre-round all GEMM weights to tf32 (RNA) once
    round_weights_kernel<<<(901120 + 255) / 256, 256>>>(lin_w, out_w, Wl0, Wr0, Wl1, Wr1, rlin);

    // input projections (K=256 -> N=64, leaky_relu 0.01, output tf32-rounded)
    gemm_tf32<1, 1, 1, 64, 4, 2><<<dim3(1, (NT + 127) / 128), 256, SMEM_BN64>>>(x_table,  rlin,          lin_b,       feat_t, NT, 256, 64);
    gemm_tf32<1, 1, 1, 64, 4, 2><<<dim3(1, (NC + 127) / 128), 256, SMEM_BN64>>>(x_column, rlin + 256*64, lin_b + 64,  feat_c, NC, 256, 64);
    gemm_tf32<1, 1, 1, 64, 4, 2><<<dim3(1, (NF + 127) / 128), 256, SMEM_BN64>>>(x_fk,     rlin + 2*256*64, lin_b + 128, feat_f, NF, 256, 64);

    for (int l = 0; l < 2; l++) {
        int Kin = (l == 0) ? 64 : 256;
        const float* Wl  = l ? rwl1 : rwl0;
        const float* Wr  = l ? rwr1 : rwr0;
        const float* att = l ? att1 : att0;
        const float* bb  = l ? b1   : b0;
        size_t ws = (size_t)Kin * FH;

        run_conv(feat_t, NT, feat_c, NC, Kin, Wl + 0 * ws, Wr + 0 * ws, att + 0,   bb + 0,
                 src_hc, dst_hc, E_HC, xl, xr, logit, seg, oc1);
        run_conv(feat_c, NC, feat_t, NT, Kin, Wl + 1 * ws, Wr + 1 * ws, att + 256, bb + 256,
                 src_bt, dst_bt, E_BT, xl, xr, logit, seg, ot);
        run_conv(feat_c, NC, feat_f, NF, Kin, Wl + 2 * ws, Wr + 2 * ws, att + 512, bb + 512,
                 src_is, dst_is, E_IS, xl, xr, logit, seg, of);
        run_conv(feat_f, NF, feat_c, NC, Kin, Wl + 3 * ws, Wr + 3 * ws, att + 768, bb + 768,
                 src_pt, dst_pt, E_PT, xl, xr, logit, seg, oc2);

        elu_kernel<<<(NT * 64 + 255) / 256, 256>>>(ot, feat_t, NT * 64);
        elu_mean_kernel<<<(NC * 64 + 255) / 256, 256>>>(oc1, oc2, feat_c, NC * 64);
        elu_kernel<<<(NF * 64 + 255) / 256, 256>>>(of, feat_f, NF * 64);
    }

    // output heads -> d_out (xt | xc | xf), fp32
    float* out = (float*)d_out;
    gemm_tf32<0, 0, 0, 128, 2, 4><<<dim3(2, (NT + 127) / 128), 256, SMEM_BN128>>>(feat_t, rout,             out_b,       out,                       NT, 256, 256);
    gemm_tf32<0, 0, 0, 128, 2, 4><<<dim3(2, (NC + 127) / 128), 256, SMEM_BN128>>>(feat_c, rout + 256*256,   out_b + 256, out + (size_t)NT * 256,    NC, 256, 256);
    gemm_tf32<0, 0, 0, 128, 2, 4><<<dim3(2, (NF + 127) / 128), 256, SMEM_BN128>>>(feat_f, rout + 2*256*256, out_b + 512, out + (size_t)(NT+NC)*256, NF, 256, 256);
}